// round 1
// baseline (speedup 1.0000x reference)
#include <cuda_runtime.h>
#include <cuda_bf16.h>

// ---------------------------------------------------------------------------
// AutomaticBrightnessAndContrast
//   image (3, H, W) fp32
//   1) max over image -> is_norm = max <= 1.0, scale = is_norm ? 255 : 1
//   2) gray = 0.299*(r*scale) + 0.587*(g*scale) + 0.114*(b*scale)
//      hist = histc(gray, 256 bins, [0,255], bin width 255/256, OOR ignored)
//   3) cumsum -> min_gray / max_gray from 0.5% clip on each side
//      alpha = 255/span, beta = -min_gray*alpha, divided by scale; clip [0,hi]
//   4) out = max_gray>min_gray ? clip(image*a+b, 0, hi) : image
// ---------------------------------------------------------------------------

#define NBINS 256
#define NSUB  4                 // shared-hist bank replicas
#define HIST_BLOCKS 1184        // 148 SMs * 8
#define HIST_THREADS 256

__device__ unsigned int g_hist[2][NBINS];   // [0]=scaled(255) hist, [1]=raw hist
__device__ unsigned int g_maxbits;          // ordered-uint encoded float max
__device__ float4       g_params;           // x=alpha_eff y=beta_eff z=hi w=flag

// monotone float -> uint map (works for all finite floats, any sign)
__device__ __forceinline__ unsigned int f2ord(float x) {
    unsigned int u = __float_as_uint(x);
    return (u & 0x80000000u) ? ~u : (u | 0x80000000u);
}
__device__ __forceinline__ float ord2f(unsigned int u) {
    unsigned int v = (u & 0x80000000u) ? (u ^ 0x80000000u) : ~u;
    return __uint_as_float(v);
}

// exact reference fp ordering: ((0.299*r)+(0.587*g))+(0.114*b), no FMA
__device__ __forceinline__ float gray_of(float r, float g, float b) {
    return __fadd_rn(__fadd_rn(__fmul_rn(0.299f, r), __fmul_rn(0.587f, g)),
                     __fmul_rn(0.114f, b));
}

// torch.histc bin index: floor(g / (255/256)), clipped, valid iff g in [0,255]
__device__ __forceinline__ void hist_add(unsigned int* sh, int sub, float g) {
    if (g >= 0.0f && g <= 255.0f) {
        int idx = (int)floorf(__fdiv_rn(g, 0.99609375f));
        idx = min(max(idx, 0), NBINS - 1);
        atomicAdd(&sh[idx * NSUB + sub], 1u);
    }
}

__global__ void init_kernel() {
    int t = blockIdx.x * blockDim.x + threadIdx.x;
    if (t < 2 * NBINS) ((unsigned int*)g_hist)[t] = 0u;
    if (t == 0) g_maxbits = 0u;
}

// Pass 1: fused global max + histogram of scaled gray (scale = 255 branch).
__global__ void __launch_bounds__(HIST_THREADS)
max_hist255_kernel(const float* __restrict__ img, int npix) {
    __shared__ unsigned int sh[NBINS * NSUB];
    int t = threadIdx.x;
    for (int k = t; k < NBINS * NSUB; k += blockDim.x) sh[k] = 0u;
    __syncthreads();

    const int sub = t & (NSUB - 1);
    const float4* rp = (const float4*)img;
    const float4* gp = (const float4*)(img + (size_t)npix);
    const float4* bp = (const float4*)(img + 2 * (size_t)npix);
    const int nvec = npix >> 2;
    float mx = -3.402823466e38f;

    for (int i = blockIdx.x * blockDim.x + t; i < nvec; i += gridDim.x * blockDim.x) {
        float4 r = rp[i], g = gp[i], b = bp[i];
        mx = fmaxf(mx, fmaxf(fmaxf(r.x, g.x), b.x));
        mx = fmaxf(mx, fmaxf(fmaxf(r.y, g.y), b.y));
        mx = fmaxf(mx, fmaxf(fmaxf(r.z, g.z), b.z));
        mx = fmaxf(mx, fmaxf(fmaxf(r.w, g.w), b.w));
        hist_add(sh, sub, gray_of(__fmul_rn(r.x, 255.0f), __fmul_rn(g.x, 255.0f), __fmul_rn(b.x, 255.0f)));
        hist_add(sh, sub, gray_of(__fmul_rn(r.y, 255.0f), __fmul_rn(g.y, 255.0f), __fmul_rn(b.y, 255.0f)));
        hist_add(sh, sub, gray_of(__fmul_rn(r.z, 255.0f), __fmul_rn(g.z, 255.0f), __fmul_rn(b.z, 255.0f)));
        hist_add(sh, sub, gray_of(__fmul_rn(r.w, 255.0f), __fmul_rn(g.w, 255.0f), __fmul_rn(b.w, 255.0f)));
    }
    // scalar tail (npix not multiple of 4)
    for (int i = (nvec << 2) + blockIdx.x * blockDim.x + t; i < npix; i += gridDim.x * blockDim.x) {
        float r = img[i], g = img[i + (size_t)npix], b = img[i + 2 * (size_t)npix];
        mx = fmaxf(mx, fmaxf(fmaxf(r, g), b));
        hist_add(sh, sub, gray_of(__fmul_rn(r, 255.0f), __fmul_rn(g, 255.0f), __fmul_rn(b, 255.0f)));
    }

    // block max -> global
    #pragma unroll
    for (int o = 16; o; o >>= 1) mx = fmaxf(mx, __shfl_xor_sync(0xffffffffu, mx, o));
    if ((t & 31) == 0) atomicMax(&g_maxbits, f2ord(mx));

    __syncthreads();
    for (int k = t; k < NBINS; k += blockDim.x) {
        unsigned int s = sh[k * NSUB] + sh[k * NSUB + 1] + sh[k * NSUB + 2] + sh[k * NSUB + 3];
        if (s) atomicAdd(&g_hist[0][k], s);
    }
}

// Pass 2 (conditional): raw-scale histogram, only if image is NOT normalized.
__global__ void __launch_bounds__(HIST_THREADS)
hist_raw_kernel(const float* __restrict__ img, int npix) {
    float maxval = ord2f(g_maxbits);
    if (maxval <= 1.0f) return;   // normalized path: nothing to do

    __shared__ unsigned int sh[NBINS * NSUB];
    int t = threadIdx.x;
    for (int k = t; k < NBINS * NSUB; k += blockDim.x) sh[k] = 0u;
    __syncthreads();

    const int sub = t & (NSUB - 1);
    const float4* rp = (const float4*)img;
    const float4* gp = (const float4*)(img + (size_t)npix);
    const float4* bp = (const float4*)(img + 2 * (size_t)npix);
    const int nvec = npix >> 2;

    for (int i = blockIdx.x * blockDim.x + t; i < nvec; i += gridDim.x * blockDim.x) {
        float4 r = rp[i], g = gp[i], b = bp[i];
        hist_add(sh, sub, gray_of(r.x, g.x, b.x));
        hist_add(sh, sub, gray_of(r.y, g.y, b.y));
        hist_add(sh, sub, gray_of(r.z, g.z, b.z));
        hist_add(sh, sub, gray_of(r.w, g.w, b.w));
    }
    for (int i = (nvec << 2) + blockIdx.x * blockDim.x + t; i < npix; i += gridDim.x * blockDim.x) {
        hist_add(sh, sub, gray_of(img[i], img[i + (size_t)npix], img[i + 2 * (size_t)npix]));
    }

    __syncthreads();
    for (int k = t; k < NBINS; k += blockDim.x) {
        unsigned int s = sh[k * NSUB] + sh[k * NSUB + 1] + sh[k * NSUB + 2] + sh[k * NSUB + 3];
        if (s) atomicAdd(&g_hist[1][k], s);
    }
}

// Pass 3: 256-bin inclusive scan + alpha/beta computation (single block).
__global__ void scan_kernel() {
    __shared__ unsigned int s[NBINS];
    __shared__ int cnt[2];
    int t = threadIdx.x;

    float maxval = ord2f(g_maxbits);
    bool is_norm = (maxval <= 1.0f);

    s[t] = is_norm ? g_hist[0][t] : g_hist[1][t];
    if (t < 2) cnt[t] = 0;
    __syncthreads();
    #pragma unroll
    for (int off = 1; off < NBINS; off <<= 1) {
        unsigned int v = (t >= off) ? s[t - off] : 0u;
        __syncthreads();
        s[t] += v;
        __syncthreads();
    }
    float accf    = (float)s[t];          // exact: counts <= 2^24
    float maximum = (float)s[NBINS - 1];

    // clip = 1.0 * (maximum/100) / 2  (all fp32, matching reference)
    float clip = __fmul_rn(__fdiv_rn(maximum, 100.0f), 0.5f);
    if (accf < clip)                       atomicAdd(&cnt[0], 1);
    if (accf < __fsub_rn(maximum, clip))   atomicAdd(&cnt[1], 1);
    __syncthreads();

    if (t == 0) {
        int min_gray = cnt[0];
        int max_gray = cnt[1] - 1;
        int spani = max(max_gray - min_gray, 1);
        float alpha = __fdiv_rn(255.0f, (float)spani);
        float beta  = __fmul_rn(-(float)min_gray, alpha);
        float scale = is_norm ? 255.0f : 1.0f;
        float4 p;
        p.x = __fdiv_rn(alpha, scale);
        p.y = __fdiv_rn(beta, scale);
        p.z = is_norm ? 1.0f : 255.0f;
        p.w = (max_gray > min_gray) ? 1.0f : 0.0f;
        g_params = p;
    }
}

// Pass 4: out = flag ? clip(x*a+b, 0, hi) : x   over all 3*npix floats.
__global__ void __launch_bounds__(256)
transform_kernel(const float4* __restrict__ in, float4* __restrict__ out,
                 int nvec, int total) {
    int i = blockIdx.x * blockDim.x + threadIdx.x;
    float4 p = g_params;
    if (i < nvec) {
        float4 x = in[i];
        if (p.w != 0.0f) {
            x.x = fminf(fmaxf(fmaf(x.x, p.x, p.y), 0.0f), p.z);
            x.y = fminf(fmaxf(fmaf(x.y, p.x, p.y), 0.0f), p.z);
            x.z = fminf(fmaxf(fmaf(x.z, p.x, p.y), 0.0f), p.z);
            x.w = fminf(fmaxf(fmaf(x.w, p.x, p.y), 0.0f), p.z);
        }
        out[i] = x;
    }
    int base = nvec << 2;
    int tail = total - base;
    if (i < tail) {
        const float* inf = (const float*)in;
        float*       of  = (float*)out;
        float v = inf[base + i];
        if (p.w != 0.0f) v = fminf(fmaxf(fmaf(v, p.x, p.y), 0.0f), p.z);
        of[base + i] = v;
    }
}

extern "C" void kernel_launch(void* const* d_in, const int* in_sizes, int n_in,
                              void* d_out, int out_size) {
    const float* img = (const float*)d_in[0];
    float* out = (float*)d_out;
    int total = in_sizes[0];          // 3 * H * W
    int npix  = total / 3;
    int nvec  = total >> 2;

    init_kernel<<<2, 256>>>();
    max_hist255_kernel<<<HIST_BLOCKS, HIST_THREADS>>>(img, npix);
    hist_raw_kernel<<<HIST_BLOCKS, HIST_THREADS>>>(img, npix);
    scan_kernel<<<1, NBINS>>>();
    transform_kernel<<<(nvec + 255) / 256, 256>>>((const float4*)img, (float4*)out,
                                                  nvec, total);
}

// round 2
// speedup vs baseline: 1.0351x; 1.0351x over previous
#include <cuda_runtime.h>
#include <cuda_bf16.h>

// ---------------------------------------------------------------------------
// AutomaticBrightnessAndContrast — 4-launch pipeline, self-cleaning scratch.
//   L1: fused global-max + 256-bin histogram of scaled gray   (reads 201 MB)
//   L2: raw-scale histogram, early-exits when image normalized (reads ~0)
//   L3: warp-scan of 256 bins -> alpha/beta; zeroes scratch for next replay
//   L4: out = clip(x*a+b, 0, hi)                               (r+w 402 MB)
// ---------------------------------------------------------------------------

#define NBINS 256
#define NSUB  4                 // shared-hist replicas
#define HIST_BLOCKS 1184        // 148 SMs * 8
#define HIST_THREADS 256

__device__ unsigned int g_hist[2][NBINS];   // [0]=scaled(255) hist, [1]=raw hist
__device__ unsigned int g_maxbits;          // ordered-uint encoded float max
__device__ float4       g_params;           // x=alpha_eff y=beta_eff z=hi w=flag

// monotone float -> uint map
__device__ __forceinline__ unsigned int f2ord(float x) {
    unsigned int u = __float_as_uint(x);
    return (u & 0x80000000u) ? ~u : (u | 0x80000000u);
}
__device__ __forceinline__ float ord2f(unsigned int u) {
    unsigned int v = (u & 0x80000000u) ? (u ^ 0x80000000u) : ~u;
    return __uint_as_float(v);
}

// exact reference fp ordering: ((0.299*r)+(0.587*g))+(0.114*b), no FMA
__device__ __forceinline__ float gray_of(float r, float g, float b) {
    return __fadd_rn(__fadd_rn(__fmul_rn(0.299f, r), __fmul_rn(0.587f, g)),
                     __fmul_rn(0.114f, b));
}

// torch.histc bin: floor(RN(g / (255/256))), clipped; valid iff g in [0,255].
// __fdiv_rn kept deliberately — bit-exact match with the reference (rel_err 0.0).
__device__ __forceinline__ void hist_add(unsigned int* sh, int sub, float g) {
    if (g >= 0.0f && g <= 255.0f) {
        int idx = (int)floorf(__fdiv_rn(g, 0.99609375f));
        idx = min(max(idx, 0), NBINS - 1);
        atomicAdd(&sh[idx * NSUB + sub], 1u);
    }
}

// Pass 1: fused global max + histogram of scaled gray (scale = 255 branch).
__global__ void __launch_bounds__(HIST_THREADS)
max_hist255_kernel(const float* __restrict__ img, int npix) {
    __shared__ unsigned int sh[NBINS * NSUB];
    int t = threadIdx.x;
    for (int k = t; k < NBINS * NSUB; k += blockDim.x) sh[k] = 0u;
    __syncthreads();

    const int sub = t & (NSUB - 1);
    const float4* rp = (const float4*)img;
    const float4* gp = (const float4*)(img + (size_t)npix);
    const float4* bp = (const float4*)(img + 2 * (size_t)npix);
    const int nvec = npix >> 2;
    float mx = -3.402823466e38f;

    for (int i = blockIdx.x * blockDim.x + t; i < nvec; i += gridDim.x * blockDim.x) {
        float4 r = rp[i], g = gp[i], b = bp[i];
        mx = fmaxf(mx, fmaxf(fmaxf(r.x, g.x), b.x));
        mx = fmaxf(mx, fmaxf(fmaxf(r.y, g.y), b.y));
        mx = fmaxf(mx, fmaxf(fmaxf(r.z, g.z), b.z));
        mx = fmaxf(mx, fmaxf(fmaxf(r.w, g.w), b.w));
        hist_add(sh, sub, gray_of(__fmul_rn(r.x, 255.0f), __fmul_rn(g.x, 255.0f), __fmul_rn(b.x, 255.0f)));
        hist_add(sh, sub, gray_of(__fmul_rn(r.y, 255.0f), __fmul_rn(g.y, 255.0f), __fmul_rn(b.y, 255.0f)));
        hist_add(sh, sub, gray_of(__fmul_rn(r.z, 255.0f), __fmul_rn(g.z, 255.0f), __fmul_rn(b.z, 255.0f)));
        hist_add(sh, sub, gray_of(__fmul_rn(r.w, 255.0f), __fmul_rn(g.w, 255.0f), __fmul_rn(b.w, 255.0f)));
    }
    for (int i = (nvec << 2) + blockIdx.x * blockDim.x + t; i < npix; i += gridDim.x * blockDim.x) {
        float r = img[i], g = img[i + (size_t)npix], b = img[i + 2 * (size_t)npix];
        mx = fmaxf(mx, fmaxf(fmaxf(r, g), b));
        hist_add(sh, sub, gray_of(__fmul_rn(r, 255.0f), __fmul_rn(g, 255.0f), __fmul_rn(b, 255.0f)));
    }

    #pragma unroll
    for (int o = 16; o; o >>= 1) mx = fmaxf(mx, __shfl_xor_sync(0xffffffffu, mx, o));
    if ((t & 31) == 0) atomicMax(&g_maxbits, f2ord(mx));

    __syncthreads();
    for (int k = t; k < NBINS; k += blockDim.x) {
        unsigned int s = sh[k * NSUB] + sh[k * NSUB + 1] + sh[k * NSUB + 2] + sh[k * NSUB + 3];
        if (s) atomicAdd(&g_hist[0][k], s);
    }
}

// Pass 2 (conditional): raw-scale histogram, only if image is NOT normalized.
__global__ void __launch_bounds__(HIST_THREADS)
hist_raw_kernel(const float* __restrict__ img, int npix) {
    float maxval = ord2f(g_maxbits);
    if (maxval <= 1.0f) return;   // normalized path: nothing to do

    __shared__ unsigned int sh[NBINS * NSUB];
    int t = threadIdx.x;
    for (int k = t; k < NBINS * NSUB; k += blockDim.x) sh[k] = 0u;
    __syncthreads();

    const int sub = t & (NSUB - 1);
    const float4* rp = (const float4*)img;
    const float4* gp = (const float4*)(img + (size_t)npix);
    const float4* bp = (const float4*)(img + 2 * (size_t)npix);
    const int nvec = npix >> 2;

    for (int i = blockIdx.x * blockDim.x + t; i < nvec; i += gridDim.x * blockDim.x) {
        float4 r = rp[i], g = gp[i], b = bp[i];
        hist_add(sh, sub, gray_of(r.x, g.x, b.x));
        hist_add(sh, sub, gray_of(r.y, g.y, b.y));
        hist_add(sh, sub, gray_of(r.z, g.z, b.z));
        hist_add(sh, sub, gray_of(r.w, g.w, b.w));
    }
    for (int i = (nvec << 2) + blockIdx.x * blockDim.x + t; i < npix; i += gridDim.x * blockDim.x) {
        hist_add(sh, sub, gray_of(img[i], img[i + (size_t)npix], img[i + 2 * (size_t)npix]));
    }

    __syncthreads();
    for (int k = t; k < NBINS; k += blockDim.x) {
        unsigned int s = sh[k * NSUB] + sh[k * NSUB + 1] + sh[k * NSUB + 2] + sh[k * NSUB + 3];
        if (s) atomicAdd(&g_hist[1][k], s);
    }
}

// Pass 3: single-warp 256-bin scan + params; zeroes scratch for next replay.
__global__ void __launch_bounds__(32)
scan_kernel() {
    const unsigned int FULL = 0xffffffffu;
    int lane = threadIdx.x;

    float maxval = ord2f(g_maxbits);
    bool is_norm = (maxval <= 1.0f);
    const unsigned int* h = is_norm ? g_hist[0] : g_hist[1];

    // lane owns bins [8*lane, 8*lane+8)
    uint4 a = ((const uint4*)h)[lane * 2];
    uint4 b = ((const uint4*)h)[lane * 2 + 1];
    unsigned int v[8] = {a.x, a.y, a.z, a.w, b.x, b.y, b.z, b.w};

    unsigned int run = 0;
    #pragma unroll
    for (int i = 0; i < 8; i++) { run += v[i]; v[i] = run; }   // local inclusive

    unsigned int inc = run;                                     // warp inclusive scan
    #pragma unroll
    for (int o = 1; o < 32; o <<= 1) {
        unsigned int n = __shfl_up_sync(FULL, inc, o);
        if (lane >= o) inc += n;
    }
    unsigned int offs  = inc - run;
    unsigned int total = __shfl_sync(FULL, inc, 31);

    float maximum = (float)total;                               // exact (< 2^24)
    float clip = __fmul_rn(__fdiv_rn(maximum, 100.0f), 0.5f);
    float thr2 = __fsub_rn(maximum, clip);

    int c0 = 0, c1 = 0;
    #pragma unroll
    for (int i = 0; i < 8; i++) {
        float acc = (float)(v[i] + offs);                       // exact
        c0 += (acc < clip);
        c1 += (acc < thr2);
    }
    #pragma unroll
    for (int o = 16; o; o >>= 1) {
        c0 += __shfl_xor_sync(FULL, c0, o);
        c1 += __shfl_xor_sync(FULL, c1, o);
    }

    if (lane == 0) {
        int min_gray = c0;
        int max_gray = c1 - 1;
        int spani = max(max_gray - min_gray, 1);
        float alpha = __fdiv_rn(255.0f, (float)spani);
        float beta  = __fmul_rn(-(float)min_gray, alpha);
        float scale = is_norm ? 255.0f : 1.0f;
        float4 p;
        p.x = __fdiv_rn(alpha, scale);
        p.y = __fdiv_rn(beta, scale);
        p.z = is_norm ? 1.0f : 255.0f;
        p.w = (max_gray > min_gray) ? 1.0f : 0.0f;
        g_params = p;
    }

    // self-clean: zero both histograms + maxbits for the next graph replay
    __syncwarp(FULL);
    uint4 z = make_uint4(0u, 0u, 0u, 0u);
    #pragma unroll
    for (int k = 0; k < 4; k++)                 // 128 uint4 = 512 uints total
        ((uint4*)g_hist)[lane + 32 * k] = z;
    if (lane == 0) g_maxbits = 0u;
}

// Pass 4: out = flag ? clip(x*a+b, 0, hi) : x   over all 3*npix floats.
__global__ void __launch_bounds__(256)
transform_kernel(const float4* __restrict__ in, float4* __restrict__ out,
                 int nvec, int total) {
    int i = blockIdx.x * blockDim.x + threadIdx.x;
    float4 p = g_params;
    if (i < nvec) {
        float4 x = in[i];
        if (p.w != 0.0f) {
            x.x = fminf(fmaxf(fmaf(x.x, p.x, p.y), 0.0f), p.z);
            x.y = fminf(fmaxf(fmaf(x.y, p.x, p.y), 0.0f), p.z);
            x.z = fminf(fmaxf(fmaf(x.z, p.x, p.y), 0.0f), p.z);
            x.w = fminf(fmaxf(fmaf(x.w, p.x, p.y), 0.0f), p.z);
        }
        out[i] = x;
    }
    int base = nvec << 2;
    int tail = total - base;
    if (i < tail) {
        const float* inf = (const float*)in;
        float*       of  = (float*)out;
        float v = inf[base + i];
        if (p.w != 0.0f) v = fminf(fmaxf(fmaf(v, p.x, p.y), 0.0f), p.z);
        of[base + i] = v;
    }
}

extern "C" void kernel_launch(void* const* d_in, const int* in_sizes, int n_in,
                              void* d_out, int out_size) {
    const float* img = (const float*)d_in[0];
    float* out = (float*)d_out;
    int total = in_sizes[0];          // 3 * H * W
    int npix  = total / 3;
    int nvec  = total >> 2;

    max_hist255_kernel<<<HIST_BLOCKS, HIST_THREADS>>>(img, npix);
    hist_raw_kernel<<<HIST_BLOCKS, HIST_THREADS>>>(img, npix);
    scan_kernel<<<1, 32>>>();
    transform_kernel<<<(nvec + 255) / 256, 256>>>((const float4*)img, (float4*)out,
                                                  nvec, total);
}